// round 2
// baseline (speedup 1.0000x reference)
#include <cuda_runtime.h>
#include <cstdint>

#define NB 4
#define NP 8192
#define ND 512
#define NS1 4096
#define NS2 2048
#define ROWS_PER_B (NP + NS1 + NS2)   /* 14336 */
#define OUTX_ELEMS ((size_t)NB * ROWS_PER_B * ND)

#define CSZ 8                          /* cluster CTAs per batch      */
#define TPB 512                        /* threads per FPS CTA (16 w)  */
#define PTS_PER_CTA (NP / CSZ)         /* 1024                        */
/* each thread owns 2 consecutive points                               */

__device__ int g_fps_idx[NB * NS1];

/* ---------------- packed f32x2 helpers (proven in round 1) -------- */
__device__ __forceinline__ unsigned long long f32x2_add(unsigned long long a, unsigned long long b) {
    unsigned long long r;
    asm("add.rn.f32x2 %0, %1, %2;" : "=l"(r) : "l"(a), "l"(b));
    return r;
}
__device__ __forceinline__ unsigned long long f32x2_mul(unsigned long long a, unsigned long long b) {
    unsigned long long r;
    asm("mul.rn.f32x2 %0, %1, %2;" : "=l"(r) : "l"(a), "l"(b));
    return r;
}
__device__ __forceinline__ unsigned long long pack2(float lo, float hi) {
    unsigned long long r;
    asm("mov.b64 %0, {%1, %2};" : "=l"(r) : "f"(lo), "f"(hi));
    return r;
}
__device__ __forceinline__ void unpack2(unsigned long long v, float& lo, float& hi) {
    asm("mov.b64 {%0, %1}, %2;" : "=f"(lo), "=f"(hi) : "l"(v));
}

/* ---------------- cluster / DSMEM helpers ------------------------- */
__device__ __forceinline__ uint32_t smem_u32(const void* p) {
    uint32_t a;
    asm("{ .reg .u64 t; cvta.to.shared.u64 t, %1; cvt.u32.u64 %0, t; }" : "=r"(a) : "l"(p));
    return a;
}
__device__ __forceinline__ uint32_t mapa_u32(uint32_t local, uint32_t rank) {
    uint32_t r;
    asm("mapa.shared::cluster.u32 %0, %1, %2;" : "=r"(r) : "r"(local), "r"(rank));
    return r;
}
__device__ __forceinline__ void st_cluster_u64(uint32_t addr, unsigned long long v) {
    asm volatile("st.relaxed.cluster.shared::cluster.b64 [%0], %1;" :: "r"(addr), "l"(v) : "memory");
}
__device__ __forceinline__ unsigned long long ld_cluster_u64(uint32_t addr) {
    unsigned long long v;
    asm volatile("ld.relaxed.cluster.shared::cta.b64 %0, [%1];" : "=l"(v) : "r"(addr));
    return v;
}
__device__ __forceinline__ void cluster_sync() {
    asm volatile("barrier.cluster.arrive.aligned;" ::: "memory");
    asm volatile("barrier.cluster.wait.aligned;" ::: "memory");
}

/* ===================================================================
   Cluster-parallel FPS: one 8-CTA cluster per batch (32 SMs total).
   Each CTA owns 1024 points (2/thread, registers). Full pos mirrored
   in each CTA's SMEM for O(1) centroid fetch regardless of owner.
   Per step:
     1. exact distance update (f32x2 add/mul, fminf) — bit-identical
        to the reference rounding (p + (-c) == p - c in RN, no FMA).
     2. warp argmax via double-redux on (valBits, invIdx) — exact
        first-occurrence tie-break (invIdx = 0xFFFFF - globalIdx).
     3. CTA reduce of 16 warp candidates (one __syncthreads).
     4. all-to-all DSMEM broadcast of the CTA candidate packed as
        [val:32 | stepTag:12 | invIdx:20]; every warp polls its own
        8 local mailbox slots and reduces redundantly (no 2nd bar).
   Mailboxes + warp-candidate arrays double-buffered by step parity:
   slot for step s is only rewritten at s+2, which transitively
   requires every CTA to have consumed step s  ->  race-free.
   =================================================================== */
__global__ void __launch_bounds__(TPB, 1) __cluster_dims__(CSZ, 1, 1)
fps_kernel(const float* __restrict__ pos)
{
    const int tid  = threadIdx.x;
    const int lane = tid & 31;
    const int wid  = tid >> 5;
    const int rank = blockIdx.x & (CSZ - 1);     /* cluster ctarank    */
    const int b    = blockIdx.x / CSZ;           /* batch              */

    extern __shared__ unsigned char smem_raw[];
    unsigned long long* cbox  = reinterpret_cast<unsigned long long*>(smem_raw);          /* [2][8]  */
    uint2*              wcand = reinterpret_cast<uint2*>(smem_raw + 128);                 /* [2][16] */
    float*              sx    = reinterpret_cast<float*>(smem_raw + 384);
    float*              sy    = sx + NP;
    float*              sz    = sy + NP;
    const uint32_t cbox_addr  = smem_u32(cbox);

    /* stage full pos for this batch; init mailboxes (tag 0 != any s) */
    const float* pb = pos + (size_t)b * NP * 3;
    for (int i = tid; i < NP; i += TPB) {
        sx[i] = pb[3 * i + 0];
        sy[i] = pb[3 * i + 1];
        sz[i] = pb[3 * i + 2];
    }
    if (tid < 2 * CSZ) cbox[tid] = 0ull;
    __syncthreads();
    cluster_sync();                 /* mailboxes valid before any remote store */

    /* thread-private points: global ids base, base+1 (monotone map)  */
    const int base = rank * PTS_PER_CTA + tid * 2;
    const unsigned inv0 = 0xFFFFFu - (unsigned)base;       /* larger = lower idx */
    const unsigned inv1 = inv0 - 1u;
    const unsigned long long px2 = pack2(sx[base], sx[base + 1]);
    const unsigned long long py2 = pack2(sy[base], sy[base + 1]);
    const unsigned long long pz2 = pack2(sz[base], sz[base + 1]);
    float dist0 = 1e10f, dist1 = 1e10f;

    int cur = 0;
    if (rank == 0 && tid == 0) g_fps_idx[b * NS1] = 0;

    for (int s = 1; s < NS1; s++) {
        /* ---- exact distance update for this thread's 2 points ---- */
        const float cx = sx[cur], cy = sy[cur], cz = sz[cur];
        const unsigned long long dx = f32x2_add(px2, pack2(-cx, -cx));
        const unsigned long long dy = f32x2_add(py2, pack2(-cy, -cy));
        const unsigned long long dz = f32x2_add(pz2, pack2(-cz, -cz));
        const unsigned long long sm = f32x2_add(
            f32x2_add(f32x2_mul(dx, dx), f32x2_mul(dy, dy)), f32x2_mul(dz, dz));
        float d0, d1;
        unpack2(sm, d0, d1);
        dist0 = fminf(dist0, d0);
        dist1 = fminf(dist1, d1);
        const float    best = fmaxf(dist0, dist1);
        const unsigned binv = (dist0 >= dist1) ? inv0 : inv1;   /* tie -> lower idx */

        /* ---- warp argmax: (val desc, idx asc) via double redux ---- */
        const unsigned vb = __float_as_uint(best);              /* dist >= 0 */
        const unsigned vm = __reduce_max_sync(0xffffffffu, vb);
        const unsigned li = __reduce_max_sync(0xffffffffu, (vb == vm) ? binv : 0u);
        const int sl = s & 1;
        if (lane == 0) wcand[(sl << 4) + wid] = make_uint2(vm, li);
        __syncthreads();

        /* ---- CTA reduce of 16 warp candidates (every warp) ------- */
        const uint2 wc = (lane < 16) ? wcand[(sl << 4) + lane] : make_uint2(0u, 0u);
        const unsigned vm2 = __reduce_max_sync(0xffffffffu, wc.x);
        const unsigned li2 = __reduce_max_sync(0xffffffffu, (wc.x == vm2) ? wc.y : 0u);

        /* ---- all-to-all cluster broadcast (warp 0, lanes 0..7) ---- */
        const unsigned tag = (unsigned)s & 0xFFFu;
        if (wid == 0 && lane < CSZ) {
            const unsigned long long pkt =
                ((unsigned long long)vm2 << 32) | (tag << 20) | li2;
            const uint32_t dst = mapa_u32(cbox_addr + ((sl << 3) + rank) * 8u, (uint32_t)lane);
            st_cluster_u64(dst, pkt);
        }

        /* ---- every warp polls its own 8 slots, reduces ------------ */
        unsigned long long got = 0ull;
        if (lane < CSZ) {
            const uint32_t a = cbox_addr + ((sl << 3) + lane) * 8u;
            do { got = ld_cluster_u64(a); }
            while (((unsigned)(got >> 20) & 0xFFFu) != tag);
        }
        const unsigned hv = (lane < CSZ) ? (unsigned)(got >> 32) : 0u;
        const unsigned vg = __reduce_max_sync(0xffffffffu, hv);
        const unsigned ig = __reduce_max_sync(0xffffffffu,
                              (lane < CSZ && hv == vg) ? ((unsigned)got & 0xFFFFFu) : 0u);
        cur = (int)(0xFFFFFu - ig);

        if (rank == 0 && tid == 0) g_fps_idx[b * NS1 + s] = cur;
    }

    cluster_sync();    /* no CTA exits while peers' stores may be in flight */
}

/* ===================================================================
   Gather: one 128-thread block per output row, one float4 per thread.
   Scale 0.25 reuses the first 2048 FPS indices (greedy prefix).
   =================================================================== */
__global__ void gather_kernel(const float* __restrict__ x,
                              const float* __restrict__ pos,
                              float* __restrict__ outx,
                              float* __restrict__ outp)
{
    const int r = blockIdx.x;
    const int b = r / ROWS_PER_B;
    const int o = r - b * ROWS_PER_B;

    int src;
    if (o < NP)             src = o;
    else if (o < NP + NS1)  src = g_fps_idx[b * NS1 + (o - NP)];
    else                    src = g_fps_idx[b * NS1 + (o - NP - NS1)];

    const size_t srow = (size_t)b * NP + (size_t)src;
    const float4* xin = reinterpret_cast<const float4*>(x + srow * ND);
    float4*       xo  = reinterpret_cast<float4*>(outx + (size_t)r * ND);
    xo[threadIdx.x] = xin[threadIdx.x];

    if (threadIdx.x < 3)
        outp[(size_t)r * 3 + threadIdx.x] = pos[srow * 3 + threadIdx.x];
}

extern "C" void kernel_launch(void* const* d_in, const int* in_sizes, int n_in,
                              void* d_out, int out_size)
{
    const float* x   = (const float*)d_in[0];   /* [B*P, D] f32 */
    const float* pos = (const float*)d_in[1];   /* [B*P, 3] f32 */

    float* outx = (float*)d_out;
    float* outp = outx + OUTX_ELEMS;

    const size_t smem_bytes = 384 + (size_t)3 * NP * sizeof(float);
    cudaFuncSetAttribute(fps_kernel, cudaFuncAttributeMaxDynamicSharedMemorySize,
                         (int)smem_bytes);

    fps_kernel<<<NB * CSZ, TPB, smem_bytes>>>(pos);
    gather_kernel<<<NB * ROWS_PER_B, 128>>>(x, pos, outx, outp);
}

// round 4
// speedup vs baseline: 2.7760x; 2.7760x over previous
#include <cuda_runtime.h>
#include <cstdint>

#define NB 4
#define NP 8192
#define ND 512
#define NS1 4096
#define NS2 2048
#define ROWS_PER_B (NP + NS1 + NS2)   /* 14336 */
#define OUTX_ELEMS ((size_t)NB * ROWS_PER_B * ND)
#define TPB 1024

/* smem layout (bytes) */
#define OFF_WCAND 0        /* uint2[64]  = 512           */
#define OFF_CNT   512      /* int ssum, int sxor         */
#define OFF_SX    1024
#define OFF_SY    (OFF_SX + NP * 4)
#define OFF_SZ    (OFF_SY + NP * 4)
#define OFF_KEY   (OFF_SZ + NP * 4)          /* u32[8192] */
#define OFF_SID   (OFF_KEY + NP * 4)         /* u16[8192] */
#define SMEM_TOTAL (OFF_SID + NP * 2)        /* 148480 B  */

__device__ int g_fps_idx[NB * NS1];

/* ---------------- packed f32x2 helpers (proven round 1) ----------- */
__device__ __forceinline__ unsigned long long f32x2_add(unsigned long long a, unsigned long long b) {
    unsigned long long r;
    asm("add.rn.f32x2 %0, %1, %2;" : "=l"(r) : "l"(a), "l"(b));
    return r;
}
__device__ __forceinline__ unsigned long long f32x2_mul(unsigned long long a, unsigned long long b) {
    unsigned long long r;
    asm("mul.rn.f32x2 %0, %1, %2;" : "=l"(r) : "l"(a), "l"(b));
    return r;
}
__device__ __forceinline__ unsigned long long pack2(float lo, float hi) {
    unsigned long long r;
    asm("mov.b64 %0, {%1, %2};" : "=l"(r) : "f"(lo), "f"(hi));
    return r;
}
__device__ __forceinline__ void unpack2(unsigned long long v, float& lo, float& hi) {
    asm("mov.b64 {%0, %1}, %2;" : "=f"(lo), "=f"(hi) : "l"(v));
}

/* ---------------- Morton helpers ---------------------------------- */
__device__ __forceinline__ unsigned expand10(unsigned v) {
    v &= 0x3FFu;
    v = (v | (v << 16)) & 0x030000FFu;
    v = (v | (v <<  8)) & 0x0300F00Fu;
    v = (v | (v <<  4)) & 0x030C30C3u;
    v = (v | (v <<  2)) & 0x09249249u;
    return v;
}
__device__ __forceinline__ unsigned quant10(float x) {
    float q = (x + 8.0f) * 64.0f;
    q = fminf(fmaxf(q, 0.0f), 1023.0f);
    return (unsigned)q;
}

/* ===================================================================
   FPS, one 1024-thread CTA per batch, with exact AABB pruning.
   - Morton sort (u32 key + u16 payload bitonic) gives each thread 8
     spatially-coherent points; a sum+xor permutation check guards the
     sort — on ANY anomaly every thread falls back to identity
     ownership (ids = 8*tid+k), i.e. the proven round-1 algorithm.
   - Per-thread candidate (tub = exact max of its 8 dists, tbid =
     first/lowest original index achieving it) is recomputed in full
     on every dirty step; skip steps provably leave dists unchanged
     (dmin2(bbox,c)*(1-1e-5) >= tub  =>  every ref update is a no-op
     under its exact rounding; margin >> accumulated 1e-6 slack).
   - Warp + CTA argmax every step via __reduce_max on dist bits and
     __reduce_min on ids among maxima -> exact first-occurrence
     semantics, independent of point->lane placement.
   - Distance arithmetic identical to round 1 (add.rn/mul.rn.f32x2,
     fminf): bit-exact vs reference.
   =================================================================== */
__global__ void __launch_bounds__(TPB, 1) fps_kernel(const float* __restrict__ pos)
{
    const int b    = blockIdx.x;
    const int tid  = threadIdx.x;
    const int lane = tid & 31;
    const int wid  = tid >> 5;

    extern __shared__ unsigned char smem_raw[];
    uint2*          wcand = reinterpret_cast<uint2*>(smem_raw + OFF_WCAND);
    int*            scnt  = reinterpret_cast<int*>(smem_raw + OFF_CNT);     /* [2] */
    float*          sx    = reinterpret_cast<float*>(smem_raw + OFF_SX);
    float*          sy    = reinterpret_cast<float*>(smem_raw + OFF_SY);
    float*          sz    = reinterpret_cast<float*>(smem_raw + OFF_SZ);
    unsigned*       skey  = reinterpret_cast<unsigned*>(smem_raw + OFF_KEY);
    unsigned short* sid   = reinterpret_cast<unsigned short*>(smem_raw + OFF_SID);

    if (tid == 0) { scnt[0] = 0; scnt[1] = 0; }

    /* ---- stage coords (original order) + Morton keys ---- */
    const float* pb = pos + (size_t)b * NP * 3;
    for (int i = tid; i < NP; i += TPB) {
        const float x = pb[3 * i + 0];
        const float y = pb[3 * i + 1];
        const float z = pb[3 * i + 2];
        sx[i] = x; sy[i] = y; sz[i] = z;
        skey[i] = expand10(quant10(x)) | (expand10(quant10(y)) << 1)
                | (expand10(quant10(z)) << 2);
        sid[i]  = (unsigned short)i;
    }
    __syncthreads();

    /* ---- bitonic sort (ascending key) of (key,u16 payload) ---- */
    for (int k = 2; k <= NP; k <<= 1) {
        for (int j = k >> 1; j > 0; j >>= 1) {
            for (int i = tid; i < NP; i += TPB) {
                const int ixj = i ^ j;
                if (ixj > i) {
                    const unsigned a = skey[i];
                    const unsigned c = skey[ixj];
                    const bool up = ((i & k) == 0);
                    if ((a > c) == up) {
                        skey[i] = c; skey[ixj] = a;
                        const unsigned short t = sid[i]; sid[i] = sid[ixj]; sid[ixj] = t;
                    }
                }
            }
            __syncthreads();
        }
    }

    /* ---- ownership + permutation validity check -------------------- */
    int ids[8];
    int psum = 0, pxor = 0;
#pragma unroll
    for (int kk = 0; kk < 8; kk++) {
        ids[kk] = (int)sid[tid * 8 + kk];
        psum += ids[kk];
        pxor ^= ids[kk];
    }
    atomicAdd(&scnt[0], psum);
    atomicXor(&scnt[1], pxor);
    __syncthreads();
    const bool perm_ok = (scnt[0] == (NP * (NP - 1) / 2)) && (scnt[1] == 0);
    if (!perm_ok) {
#pragma unroll
        for (int kk = 0; kk < 8; kk++) ids[kk] = tid * 8 + kk;   /* round-1 fallback */
    }

    /* sort ids ascending (Batcher 8-network) -> in-thread strict '>'
       tie-break yields first (lowest) original index                    */
#define CSWP(a, bb) { if (ids[a] > ids[bb]) { int t = ids[a]; ids[a] = ids[bb]; ids[bb] = t; } }
    CSWP(0,1) CSWP(2,3) CSWP(4,5) CSWP(6,7)
    CSWP(0,2) CSWP(1,3) CSWP(4,6) CSWP(5,7)
    CSWP(1,2) CSWP(5,6)
    CSWP(0,4) CSWP(1,5) CSWP(2,6) CSWP(3,7)
    CSWP(1,4) CSWP(3,6)
    CSWP(2,4) CSWP(3,5)
    CSWP(3,4)
#undef CSWP

    /* ---- load owned points into registers, build bbox -------------- */
    unsigned long long px2[4], py2[4], pz2[4];
    float dist[8];
    float bxlo, bxhi, bylo, byhi, bzlo, bzhi;
    {
        float lx0 = sx[ids[0]], ly0 = sy[ids[0]], lz0 = sz[ids[0]];
        bxlo = bxhi = lx0; bylo = byhi = ly0; bzlo = bzhi = lz0;
        float lxp = lx0, lyp = ly0, lzp = lz0;
#pragma unroll
        for (int kk = 0; kk < 8; kk++) {
            const float lx = sx[ids[kk]], ly = sy[ids[kk]], lz = sz[ids[kk]];
            bxlo = fminf(bxlo, lx); bxhi = fmaxf(bxhi, lx);
            bylo = fminf(bylo, ly); byhi = fmaxf(byhi, ly);
            bzlo = fminf(bzlo, lz); bzhi = fmaxf(bzhi, lz);
            if (kk & 1) {
                px2[kk >> 1] = pack2(lxp, lx);
                py2[kk >> 1] = pack2(lyp, ly);
                pz2[kk >> 1] = pack2(lzp, lz);
            }
            lxp = lx; lyp = ly; lzp = lz;
            dist[kk] = 1e10f;
        }
    }

    float tub  = 1e10f;    /* exact max of this thread's dists          */
    int   tbid = ids[0];   /* first original index achieving that max   */

    int cur = 0;
    if (tid == 0) g_fps_idx[b * NS1] = 0;

    for (int s = 1; s < NS1; s++) {
        const float cx = sx[cur], cy = sy[cur], cz = sz[cur];    /* LDS bcast */

        /* exact-safe skip test: lower-bound distance from c to bbox */
        const float ddx = cx - fminf(fmaxf(cx, bxlo), bxhi);
        const float ddy = cy - fminf(fmaxf(cy, bylo), byhi);
        const float ddz = cz - fminf(fmaxf(cz, bzlo), bzhi);
        const float dmin2 = ddx * ddx + ddy * ddy + ddz * ddz;
        const bool  skip  = (dmin2 * 0.99999f >= tub);

        if (__any_sync(0xffffffffu, !skip)) {
            const unsigned long long ncx = pack2(-cx, -cx);
            const unsigned long long ncy = pack2(-cy, -cy);
            const unsigned long long ncz = pack2(-cz, -cz);
            float best = -1.0f; int bi = ids[0];
#pragma unroll
            for (int kk = 0; kk < 4; kk++) {
                /* p + (-c) == p - c (RN); separate mul/add roundings == ref */
                const unsigned long long dx = f32x2_add(px2[kk], ncx);
                const unsigned long long dy = f32x2_add(py2[kk], ncy);
                const unsigned long long dz = f32x2_add(pz2[kk], ncz);
                const unsigned long long sm = f32x2_add(
                    f32x2_add(f32x2_mul(dx, dx), f32x2_mul(dy, dy)), f32x2_mul(dz, dz));
                float d0, d1;
                unpack2(sm, d0, d1);
                const float n0 = fminf(dist[2 * kk], d0);     dist[2 * kk] = n0;
                if (n0 > best) { best = n0; bi = ids[2 * kk]; }      /* strict > */
                const float n1 = fminf(dist[2 * kk + 1], d1); dist[2 * kk + 1] = n1;
                if (n1 > best) { best = n1; bi = ids[2 * kk + 1]; }
            }
            tub = best; tbid = bi;
        }
        /* skip-step: dists provably unchanged -> (tub, tbid) still exact */

        /* warp argmax every step: (val desc, id asc) */
        const unsigned vb = __float_as_uint(tub);                 /* dist >= 0 */
        const unsigned vm = __reduce_max_sync(0xffffffffu, vb);
        const unsigned im = __reduce_min_sync(0xffffffffu,
                              (vb == vm) ? (unsigned)tbid : 0xFFFFFFFFu);
        const int sl = s & 1;
        if (lane == 0) wcand[(sl << 5) + wid] = make_uint2(vm, im);
        __syncthreads();

        /* every warp redundantly reduces the 32 warp candidates */
        const uint2 wc = wcand[(sl << 5) + lane];
        const unsigned vm2 = __reduce_max_sync(0xffffffffu, wc.x);
        const unsigned im2 = __reduce_min_sync(0xffffffffu,
                               (wc.x == vm2) ? wc.y : 0xFFFFFFFFu);
        cur = (int)im2;

        if (tid == 0) g_fps_idx[b * NS1 + s] = cur;
    }
}

/* ===================================================================
   Gather: one 128-thread block per output row, one float4 per thread.
   Scale 0.25 reuses the first 2048 FPS indices (greedy prefix).
   =================================================================== */
__global__ void gather_kernel(const float* __restrict__ x,
                              const float* __restrict__ pos,
                              float* __restrict__ outx,
                              float* __restrict__ outp)
{
    const int r = blockIdx.x;
    const int b = r / ROWS_PER_B;
    const int o = r - b * ROWS_PER_B;

    int src;
    if (o < NP)             src = o;
    else if (o < NP + NS1)  src = g_fps_idx[b * NS1 + (o - NP)];
    else                    src = g_fps_idx[b * NS1 + (o - NP - NS1)];

    const size_t srow = (size_t)b * NP + (size_t)src;
    const float4* xin = reinterpret_cast<const float4*>(x + srow * ND);
    float4*       xo  = reinterpret_cast<float4*>(outx + (size_t)r * ND);
    xo[threadIdx.x] = xin[threadIdx.x];

    if (threadIdx.x < 3)
        outp[(size_t)r * 3 + threadIdx.x] = pos[srow * 3 + threadIdx.x];
}

extern "C" void kernel_launch(void* const* d_in, const int* in_sizes, int n_in,
                              void* d_out, int out_size)
{
    const float* x   = (const float*)d_in[0];   /* [B*P, D] f32 */
    const float* pos = (const float*)d_in[1];   /* [B*P, 3] f32 */

    float* outx = (float*)d_out;
    float* outp = outx + OUTX_ELEMS;

    cudaFuncSetAttribute(fps_kernel, cudaFuncAttributeMaxDynamicSharedMemorySize,
                         SMEM_TOTAL);

    fps_kernel<<<NB, TPB, SMEM_TOTAL>>>(pos);
    gather_kernel<<<NB * ROWS_PER_B, 128>>>(x, pos, outx, outp);
}